// round 13
// baseline (speedup 1.0000x reference)
#include <cuda_runtime.h>

#define NN 100000
#define NE 3200000
#define HH 32
#define EMBD 16
#define NCAT 141
#define OS 64   // g_out row stride (floats): [0..31] feats | [32..35] aux (den, sc_sum, sc_cnt, pad)

// ---------------- device scratch (static, no allocation) ----------------
__device__ float    g_H[NCAT * HH];             // 141 distinct h rows = emb @ W1
__device__ float    g_HS[NCAT];                 // H · as1 per category
__device__ float    g_HD[NCAT];                 // H · ad1 per category
__device__ float    g_hd[NN];                   // layer-2 h2·ad2
__device__ float    g_loop[NN];                 // self-loop attr
__device__ __align__(256) float g_out[NN * OS]; // layer-1 agg + aux, line-aligned rows
__device__ float2   g_sp[NN];                   // layer-2 (h2·as2, h2·Wl)
__device__ float2   g_acc2[NN];                 // layer-2 (num, den)
__device__ float    g_ce[3];                    // ce1, ce2, b2·Wl + bl
__device__ float    g_cs[HH];                   // W2 · as2
__device__ float    g_cd[HH];                   // W2 · ad2
__device__ float    g_cp[HH];                   // W2 · Wl

// ---------------- vector reduction helpers (sm_90+) ----------------
__device__ __forceinline__ void red_add_v4(float* p, float4 v) {
    asm volatile("red.global.add.v4.f32 [%0], {%1,%2,%3,%4};"
                 :: "l"(p), "f"(v.x), "f"(v.y), "f"(v.z), "f"(v.w) : "memory");
}
__device__ __forceinline__ void red_add_v2(float* p, float2 v) {
    asm volatile("red.global.add.v2.f32 [%0], {%1,%2};"
                 :: "l"(p), "f"(v.x), "f"(v.y) : "memory");
}

// ---------------- kernels ----------------

// one block: category tables + collapsed constants
__global__ void k_init(const float* emb, const float* W1,
                       const float* as1, const float* ad1,
                       const float* We1, const float* ae1,
                       const float* We2, const float* ae2,
                       const float* b2,  const float* Wl, const float* bl,
                       const float* W2,  const float* as2, const float* ad2) {
    int t = threadIdx.x;
    // H = emb @ W1  (141x16 @ 16x32)
    for (int i = t; i < NCAT * HH; i += blockDim.x) {
        int c = i >> 5, k = i & 31;
        float acc = 0.f;
        const float* er = emb + c * EMBD;
#pragma unroll
        for (int j = 0; j < EMBD; j++) acc = fmaf(er[j], W1[j * HH + k], acc);
        g_H[i] = acc;
    }
    __syncthreads();
    // HS/HD per category
    for (int c = t; c < NCAT; c += blockDim.x) {
        float hs = 0.f, hd = 0.f;
        const float* hr = g_H + c * HH;
        for (int j = 0; j < HH; j++) {
            hs = fmaf(hr[j], as1[j], hs);
            hd = fmaf(hr[j], ad1[j], hd);
        }
        g_HS[c] = hs; g_HD[c] = hd;
    }
    // scalars
    if (t == 0) {
        float c0 = 0.f, c1 = 0.f, c2 = bl[0];
        for (int j = 0; j < HH; j++) {
            c0 += We1[j] * ae1[j];
            c1 += We2[j] * ae2[j];
            c2 += b2[j] * Wl[j];
        }
        g_ce[0] = c0; g_ce[1] = c1; g_ce[2] = c2;
    }
    // collapsed layer-2 projection vectors
    if (t >= 32 && t < 32 + HH) {
        int k = t - 32;
        float cs = 0.f, cd = 0.f, cp = 0.f;
        const float* wr = W2 + k * HH;
        for (int j = 0; j < HH; j++) {
            float w = wr[j];
            cs = fmaf(w, as2[j], cs);
            cd = fmaf(w, ad2[j], cd);
            cp = fmaf(w, Wl[j],  cp);
        }
        g_cs[k] = cs; g_cd[k] = cd; g_cp[k] = cp;
    }
}

// zero used part of g_out rows (9 float4 per row)
__global__ void k_zero() {
    int i = blockIdx.x * blockDim.x + threadIdx.x;
    if (i >= NN * 9) return;
    int r = i / 9, j = i % 9;
    reinterpret_cast<float4*>(g_out + r * OS)[j] = make_float4(0.f, 0.f, 0.f, 0.f);
}

// zero layer-2 accumulators
__global__ void k_zacc() {
    int i = blockIdx.x * blockDim.x + threadIdx.x;
    if (i < NN) g_acc2[i] = make_float2(0.f, 0.f);
}

// layer-1 fused edge pass, 8 lanes/edge, category tables in SMEM:
//   ex = exp(lrelu(HS[cat[s]] + HD[cat[d]] + ea*ce0))
//   out[d,0:32] += ex * H[cat[s],:]   (features from smem, no global gather)
//   aux[d] += (ex, ea, 1, 0)
__global__ void k_edge1(const int* __restrict__ src, const int* __restrict__ dst,
                        const float* __restrict__ ea, const int* __restrict__ x_idx) {
    __shared__ float sH[NCAT * HH];
    __shared__ float sHS[NCAT], sHD[NCAT];
    int t = threadIdx.x;
    for (int i = t; i < NCAT * HH; i += blockDim.x) sH[i] = g_H[i];
    if (t < NCAT) { sHS[t] = g_HS[t]; sHD[t] = g_HD[t]; }
    __syncthreads();
    long long tt = (long long)blockIdx.x * blockDim.x + t;
    int e = (int)(tt >> 3);
    if (e >= NE) return;
    int lane = t & 31;
    int q = lane & 7;
    int cs = 0, d = 0;
    float ex = 0.f;
    if (q == 0) {
        int s = src[e];
        d = dst[e];
        cs = x_idx[s];                  // 4B random gather
        int cd = x_idx[d];              // 4B random gather
        float a = ea[e];
        float al = sHS[cs] + sHD[cd] + a * g_ce[0];
        al = (al > 0.f) ? al : 0.2f * al;
        ex = __expf(al);
        red_add_v4(g_out + d * OS + 32, make_float4(ex, a, 1.f, 0.f));
    }
    int ld = lane & ~7;                 // grid exact multiple: all lanes alive
    cs = __shfl_sync(0xffffffffu, cs, ld);
    d  = __shfl_sync(0xffffffffu, d,  ld);
    ex = __shfl_sync(0xffffffffu, ex, ld);
    float4 hv = *reinterpret_cast<const float4*>(sH + cs * HH + q * 4);  // smem, conflict-free
    hv.x *= ex; hv.y *= ex; hv.z *= ex; hv.w *= ex;
    red_add_v4(g_out + d * OS + q * 4, hv);
}

// normalize layer 1 (+ self-loop), relu(.+b1); collapsed layer-2 projections
__global__ void k_mid(const float* __restrict__ b1, const int* __restrict__ x_idx) {
    int t = threadIdx.x;
    int n = (blockIdx.x * blockDim.x + t) >> 5;
    int lane = t & 31;
    if (n >= NN) return;
    int c = x_idx[n];                   // uniform across warp (broadcast load)
    float4 aux = make_float4(0.f, 0.f, 0.f, 0.f);
    if (lane == 0)
        aux = *reinterpret_cast<const float4*>(g_out + n * OS + 32);
    float den  = __shfl_sync(0xffffffffu, aux.x, 0);
    float scx  = __shfl_sync(0xffffffffu, aux.y, 0);
    float scc  = __shfl_sync(0xffffffffu, aux.z, 0);
    float loop = scx / fmaxf(scc, 1.f);
    float al = g_HS[c] + g_HD[c] + loop * g_ce[0];
    al = (al > 0.f) ? al : 0.2f * al;
    float exs = __expf(al);
    float hn = g_H[c * HH + lane];      // hot 18KB table, L2/L1 resident
    float v = (g_out[n * OS + lane] + exs * hn) / (den + exs + 1e-16f);
    v = fmaxf(v + b1[lane], 0.f);
    float s2 = v * g_cs[lane];
    float d2 = v * g_cd[lane];
    float p  = v * g_cp[lane];
    for (int o = 16; o; o >>= 1) {
        s2 += __shfl_xor_sync(0xffffffffu, s2, o);
        d2 += __shfl_xor_sync(0xffffffffu, d2, o);
        p  += __shfl_xor_sync(0xffffffffu, p,  o);
    }
    if (lane == 0) {
        g_sp[n] = make_float2(s2, p);
        g_hd[n] = d2;
        g_loop[n] = loop;
    }
}

// layer-2 edge pass, 1 thread/edge (scalar projection)
__global__ void k_edge2(const int* __restrict__ src, const int* __restrict__ dst,
                        const float* __restrict__ ea) {
    int e = blockIdx.x * blockDim.x + threadIdx.x;
    if (e >= NE) return;
    int s = src[e], d = dst[e];
    float2 sp = g_sp[s];
    float al = sp.x + g_hd[d] + ea[e] * g_ce[1];
    al = (al > 0.f) ? al : 0.2f * al;
    float ex = __expf(al);
    red_add_v2(&g_acc2[d].x, make_float2(ex * sp.y, ex));
}

// final: add self-loop, normalize, add (b2·Wl + bl)
__global__ void k_final(float* __restrict__ out) {
    int n = blockIdx.x * blockDim.x + threadIdx.x;
    if (n >= NN) return;
    float2 sp = g_sp[n];
    float al = sp.x + g_hd[n] + g_loop[n] * g_ce[1];
    al = (al > 0.f) ? al : 0.2f * al;
    float exs = __expf(al);
    float2 acc = g_acc2[n];
    out[n] = (acc.x + exs * sp.y) / (acc.y + exs + 1e-16f) + g_ce[2];
}

// ---------------- launch ----------------
extern "C" void kernel_launch(void* const* d_in, const int* in_sizes, int n_in,
                              void* d_out, int out_size) {
    const int*   x_idx = (const int*)  d_in[0];
    const int*   ei    = (const int*)  d_in[1];
    const float* ea    = (const float*)d_in[2];
    const float* emb   = (const float*)d_in[3];
    const float* W1    = (const float*)d_in[4];
    const float* as1   = (const float*)d_in[5];
    const float* ad1   = (const float*)d_in[6];
    const float* We1   = (const float*)d_in[7];
    const float* ae1   = (const float*)d_in[8];
    const float* b1    = (const float*)d_in[9];
    const float* W2    = (const float*)d_in[10];
    const float* as2   = (const float*)d_in[11];
    const float* ad2   = (const float*)d_in[12];
    const float* We2   = (const float*)d_in[13];
    const float* ae2   = (const float*)d_in[14];
    const float* b2    = (const float*)d_in[15];
    const float* Wl    = (const float*)d_in[16];
    const float* bl    = (const float*)d_in[17];
    float* out = (float*)d_out;

    const int* src = ei;
    const int* dst = ei + NE;

    const int TB = 256;
    const int gN   = (NN + TB - 1) / TB;
    const int gE   = (NE + TB - 1) / TB;
    const int gNW  = (NN * 32 + TB - 1) / TB;                     // warp per node
    const int gED1 = (int)(((long long)NE * 8 + TB - 1) / TB);    // 8 lanes per edge
    const int gZ   = (NN * 9 + TB - 1) / TB;

    k_init<<<1, 256>>>(emb, W1, as1, ad1, We1, ae1, We2, ae2, b2, Wl, bl, W2, as2, ad2);
    k_zero<<<gZ, TB>>>();
    k_zacc<<<gN, TB>>>();

    // layer 1 (4th launch -> profiled)
    k_edge1<<<gED1, TB>>>(src, dst, ea, x_idx);
    k_mid<<<gNW, TB>>>(b1, x_idx);

    // layer 2
    k_edge2<<<gE, TB>>>(src, dst, ea);
    k_final<<<gN, TB>>>(out);
}

// round 14
// speedup vs baseline: 1.0156x; 1.0156x over previous
#include <cuda_runtime.h>

#define NN 100000
#define NE 3200000
#define HH 32
#define EMBD 16
#define NCAT 141
#define OS 64   // g_out row stride (floats): [0..31] feats | [32..35] aux (den, sc_sum, sc_cnt, pad)
#define E1B 1000  // persistent blocks for k_edge1 (25.6M items / 256000 thr = 100 uniform iters)

// ---------------- device scratch (static, no allocation) ----------------
__device__ float    g_H[NCAT * HH];             // 141 distinct h rows = emb @ W1
__device__ float    g_HS[NCAT];                 // H · as1 per category
__device__ float    g_HD[NCAT];                 // H · ad1 per category
__device__ float    g_hd[NN];                   // layer-2 h2·ad2
__device__ float    g_loop[NN];                 // self-loop attr
__device__ __align__(256) float g_out[NN * OS]; // layer-1 agg + aux, line-aligned rows
__device__ float2   g_sp[NN];                   // layer-2 (h2·as2, h2·Wl)
__device__ float2   g_acc2[NN];                 // layer-2 (num, den)
__device__ float    g_ce[3];                    // ce1, ce2, b2·Wl + bl
__device__ float    g_cs[HH];                   // W2 · as2
__device__ float    g_cd[HH];                   // W2 · ad2
__device__ float    g_cp[HH];                   // W2 · Wl

// ---------------- vector reduction helpers (sm_90+) ----------------
__device__ __forceinline__ void red_add_v4(float* p, float4 v) {
    asm volatile("red.global.add.v4.f32 [%0], {%1,%2,%3,%4};"
                 :: "l"(p), "f"(v.x), "f"(v.y), "f"(v.z), "f"(v.w) : "memory");
}
__device__ __forceinline__ void red_add_v2(float* p, float2 v) {
    asm volatile("red.global.add.v2.f32 [%0], {%1,%2};"
                 :: "l"(p), "f"(v.x), "f"(v.y) : "memory");
}

// ---------------- kernels ----------------

// one block: category tables + collapsed constants
__global__ void k_init(const float* emb, const float* W1,
                       const float* as1, const float* ad1,
                       const float* We1, const float* ae1,
                       const float* We2, const float* ae2,
                       const float* b2,  const float* Wl, const float* bl,
                       const float* W2,  const float* as2, const float* ad2) {
    int t = threadIdx.x;
    // H = emb @ W1  (141x16 @ 16x32)
    for (int i = t; i < NCAT * HH; i += blockDim.x) {
        int c = i >> 5, k = i & 31;
        float acc = 0.f;
        const float* er = emb + c * EMBD;
#pragma unroll
        for (int j = 0; j < EMBD; j++) acc = fmaf(er[j], W1[j * HH + k], acc);
        g_H[i] = acc;
    }
    __syncthreads();
    // HS/HD per category
    for (int c = t; c < NCAT; c += blockDim.x) {
        float hs = 0.f, hd = 0.f;
        const float* hr = g_H + c * HH;
        for (int j = 0; j < HH; j++) {
            hs = fmaf(hr[j], as1[j], hs);
            hd = fmaf(hr[j], ad1[j], hd);
        }
        g_HS[c] = hs; g_HD[c] = hd;
    }
    // scalars
    if (t == 0) {
        float c0 = 0.f, c1 = 0.f, c2 = bl[0];
        for (int j = 0; j < HH; j++) {
            c0 += We1[j] * ae1[j];
            c1 += We2[j] * ae2[j];
            c2 += b2[j] * Wl[j];
        }
        g_ce[0] = c0; g_ce[1] = c1; g_ce[2] = c2;
    }
    // collapsed layer-2 projection vectors
    if (t >= 32 && t < 32 + HH) {
        int k = t - 32;
        float cs = 0.f, cd = 0.f, cp = 0.f;
        const float* wr = W2 + k * HH;
        for (int j = 0; j < HH; j++) {
            float w = wr[j];
            cs = fmaf(w, as2[j], cs);
            cd = fmaf(w, ad2[j], cd);
            cp = fmaf(w, Wl[j],  cp);
        }
        g_cs[k] = cs; g_cd[k] = cd; g_cp[k] = cp;
    }
}

// zero used part of g_out rows (9 float4 per row)
__global__ void k_zero() {
    int i = blockIdx.x * blockDim.x + threadIdx.x;
    if (i >= NN * 9) return;
    int r = i / 9, j = i % 9;
    reinterpret_cast<float4*>(g_out + r * OS)[j] = make_float4(0.f, 0.f, 0.f, 0.f);
}

// zero layer-2 accumulators
__global__ void k_zacc() {
    int i = blockIdx.x * blockDim.x + threadIdx.x;
    if (i < NN) g_acc2[i] = make_float2(0.f, 0.f);
}

// layer-1 fused edge pass, PERSISTENT blocks, 8 lanes/edge, category table in SMEM
// (filled once per block, amortized over ~100 iterations):
//   ex = exp(lrelu(HS[cat[s]] + HD[cat[d]] + ea*ce0))
//   out[d,0:32] += ex * H[cat[s],:]  ;  aux[d] += (ex, ea, 1, 0)
__global__ void k_edge1(const int* __restrict__ src, const int* __restrict__ dst,
                        const float* __restrict__ ea, const int* __restrict__ x_idx) {
    __shared__ float sH[NCAT * HH];
    __shared__ float sHS[NCAT], sHD[NCAT];
    int t = threadIdx.x;
    for (int i = t; i < NCAT * HH; i += blockDim.x) sH[i] = g_H[i];
    if (t < NCAT) { sHS[t] = g_HS[t]; sHD[t] = g_HD[t]; }
    __syncthreads();
    int lane = t & 31;
    int q = lane & 7;
    int ld = lane & ~7;
    float ce0 = g_ce[0];
    const long long total = (long long)NE * 8;
    const long long stride = (long long)E1B * 256;
    // total % stride == 0 -> every iteration has all 32 lanes alive (shfl-safe)
    for (long long idx = (long long)blockIdx.x * 256 + t; idx < total; idx += stride) {
        int e = (int)(idx >> 3);
        int cs = 0, d = 0;
        float ex = 0.f;
        if (q == 0) {
            int s = src[e];
            d = dst[e];
            cs = x_idx[s];                  // 4B random gather
            int cd = x_idx[d];              // 4B random gather
            float a = ea[e];
            float al = sHS[cs] + sHD[cd] + a * ce0;
            al = (al > 0.f) ? al : 0.2f * al;
            ex = __expf(al);
            red_add_v4(g_out + d * OS + 32, make_float4(ex, a, 1.f, 0.f));
        }
        cs = __shfl_sync(0xffffffffu, cs, ld);
        d  = __shfl_sync(0xffffffffu, d,  ld);
        ex = __shfl_sync(0xffffffffu, ex, ld);
        float4 hv = *reinterpret_cast<const float4*>(sH + cs * HH + q * 4);  // smem
        hv.x *= ex; hv.y *= ex; hv.z *= ex; hv.w *= ex;
        red_add_v4(g_out + d * OS + q * 4, hv);
    }
}

// normalize layer 1 (+ self-loop), relu(.+b1); collapsed layer-2 projections
__global__ void k_mid(const float* __restrict__ b1, const int* __restrict__ x_idx) {
    int t = threadIdx.x;
    int n = (blockIdx.x * blockDim.x + t) >> 5;
    int lane = t & 31;
    if (n >= NN) return;
    int c = x_idx[n];                   // uniform across warp
    float4 aux = make_float4(0.f, 0.f, 0.f, 0.f);
    if (lane == 0)
        aux = *reinterpret_cast<const float4*>(g_out + n * OS + 32);
    float den  = __shfl_sync(0xffffffffu, aux.x, 0);
    float scx  = __shfl_sync(0xffffffffu, aux.y, 0);
    float scc  = __shfl_sync(0xffffffffu, aux.z, 0);
    float loop = scx / fmaxf(scc, 1.f);
    float al = g_HS[c] + g_HD[c] + loop * g_ce[0];
    al = (al > 0.f) ? al : 0.2f * al;
    float exs = __expf(al);
    float hn = g_H[c * HH + lane];      // hot 18KB table, cache resident
    float v = (g_out[n * OS + lane] + exs * hn) / (den + exs + 1e-16f);
    v = fmaxf(v + b1[lane], 0.f);
    float s2 = v * g_cs[lane];
    float d2 = v * g_cd[lane];
    float p  = v * g_cp[lane];
    for (int o = 16; o; o >>= 1) {
        s2 += __shfl_xor_sync(0xffffffffu, s2, o);
        d2 += __shfl_xor_sync(0xffffffffu, d2, o);
        p  += __shfl_xor_sync(0xffffffffu, p,  o);
    }
    if (lane == 0) {
        g_sp[n] = make_float2(s2, p);
        g_hd[n] = d2;
        g_loop[n] = loop;
    }
}

// layer-2 edge pass, 1 thread/edge (scalar projection)
__global__ void k_edge2(const int* __restrict__ src, const int* __restrict__ dst,
                        const float* __restrict__ ea) {
    int e = blockIdx.x * blockDim.x + threadIdx.x;
    if (e >= NE) return;
    int s = src[e], d = dst[e];
    float2 sp = g_sp[s];
    float al = sp.x + g_hd[d] + ea[e] * g_ce[1];
    al = (al > 0.f) ? al : 0.2f * al;
    float ex = __expf(al);
    red_add_v2(&g_acc2[d].x, make_float2(ex * sp.y, ex));
}

// final: add self-loop, normalize, add (b2·Wl + bl)
__global__ void k_final(float* __restrict__ out) {
    int n = blockIdx.x * blockDim.x + threadIdx.x;
    if (n >= NN) return;
    float2 sp = g_sp[n];
    float al = sp.x + g_hd[n] + g_loop[n] * g_ce[1];
    al = (al > 0.f) ? al : 0.2f * al;
    float exs = __expf(al);
    float2 acc = g_acc2[n];
    out[n] = (acc.x + exs * sp.y) / (acc.y + exs + 1e-16f) + g_ce[2];
}

// ---------------- launch ----------------
extern "C" void kernel_launch(void* const* d_in, const int* in_sizes, int n_in,
                              void* d_out, int out_size) {
    const int*   x_idx = (const int*)  d_in[0];
    const int*   ei    = (const int*)  d_in[1];
    const float* ea    = (const float*)d_in[2];
    const float* emb   = (const float*)d_in[3];
    const float* W1    = (const float*)d_in[4];
    const float* as1   = (const float*)d_in[5];
    const float* ad1   = (const float*)d_in[6];
    const float* We1   = (const float*)d_in[7];
    const float* ae1   = (const float*)d_in[8];
    const float* b1    = (const float*)d_in[9];
    const float* W2    = (const float*)d_in[10];
    const float* as2   = (const float*)d_in[11];
    const float* ad2   = (const float*)d_in[12];
    const float* We2   = (const float*)d_in[13];
    const float* ae2   = (const float*)d_in[14];
    const float* b2    = (const float*)d_in[15];
    const float* Wl    = (const float*)d_in[16];
    const float* bl    = (const float*)d_in[17];
    float* out = (float*)d_out;

    const int* src = ei;
    const int* dst = ei + NE;

    const int TB = 256;
    const int gN  = (NN + TB - 1) / TB;
    const int gE  = (NE + TB - 1) / TB;
    const int gNW = (NN * 32 + TB - 1) / TB;   // warp per node
    const int gZ  = (NN * 9 + TB - 1) / TB;

    k_init<<<1, 256>>>(emb, W1, as1, ad1, We1, ae1, We2, ae2, b2, Wl, bl, W2, as2, ad2);
    k_zero<<<gZ, TB>>>();
    k_zacc<<<gN, TB>>>();

    // layer 1 (4th launch -> profiled)
    k_edge1<<<E1B, TB>>>(src, dst, ea, x_idx);
    k_mid<<<gNW, TB>>>(b1, x_idx);

    // layer 2
    k_edge2<<<gE, TB>>>(src, dst, ea);
    k_final<<<gN, TB>>>(out);
}

// round 15
// speedup vs baseline: 1.8001x; 1.7725x over previous
#include <cuda_runtime.h>

#define NN 100000
#define NE 3200000
#define HH 32
#define EMBD 16
#define NCAT 141
#define OS 32   // g_out row stride (floats) = 128B line: [0..15] emb-acc | [16..19] aux | pad

// ---------------- device scratch (static, no allocation) ----------------
__device__ float    g_H[NCAT * HH];             // emb @ W1 (init-time only)
__device__ float    g_HS[NCAT];                 // H · as1 per category (L1-resident)
__device__ float    g_HD[NCAT];                 // H · ad1 per category (L1-resident)
__device__ float    g_hd[NN];                   // layer-2 h2·ad2
__device__ float    g_loop[NN];                 // self-loop attr
__device__ __align__(128) float g_out[NN * OS]; // one 128B line per dst
__device__ float2   g_sp[NN];                   // layer-2 (h2·as2, h2·Wl)
__device__ float2   g_acc2[NN];                 // layer-2 (num, den)
__device__ float    g_ce[3];                    // ce1, ce2, b2·Wl + bl
__device__ float    g_cs[HH];                   // W2 · as2
__device__ float    g_cd[HH];                   // W2 · ad2
__device__ float    g_cp[HH];                   // W2 · Wl

// ---------------- vector reduction helpers (sm_90+) ----------------
__device__ __forceinline__ void red_add_v4(float* p, float4 v) {
    asm volatile("red.global.add.v4.f32 [%0], {%1,%2,%3,%4};"
                 :: "l"(p), "f"(v.x), "f"(v.y), "f"(v.z), "f"(v.w) : "memory");
}
__device__ __forceinline__ void red_add_v2(float* p, float2 v) {
    asm volatile("red.global.add.v2.f32 [%0], {%1,%2};"
                 :: "l"(p), "f"(v.x), "f"(v.y) : "memory");
}

// ---------------- kernels ----------------

// one block: category tables + collapsed constants
__global__ void k_init(const float* emb, const float* W1,
                       const float* as1, const float* ad1,
                       const float* We1, const float* ae1,
                       const float* We2, const float* ae2,
                       const float* b2,  const float* Wl, const float* bl,
                       const float* W2,  const float* as2, const float* ad2) {
    int t = threadIdx.x;
    // H = emb @ W1  (141x16 @ 16x32)
    for (int i = t; i < NCAT * HH; i += blockDim.x) {
        int c = i >> 5, k = i & 31;
        float acc = 0.f;
        const float* er = emb + c * EMBD;
#pragma unroll
        for (int j = 0; j < EMBD; j++) acc = fmaf(er[j], W1[j * HH + k], acc);
        g_H[i] = acc;
    }
    __syncthreads();
    // HS/HD per category
    for (int c = t; c < NCAT; c += blockDim.x) {
        float hs = 0.f, hd = 0.f;
        const float* hr = g_H + c * HH;
        for (int j = 0; j < HH; j++) {
            hs = fmaf(hr[j], as1[j], hs);
            hd = fmaf(hr[j], ad1[j], hd);
        }
        g_HS[c] = hs; g_HD[c] = hd;
    }
    if (t == 0) {
        float c0 = 0.f, c1 = 0.f, c2 = bl[0];
        for (int j = 0; j < HH; j++) {
            c0 += We1[j] * ae1[j];
            c1 += We2[j] * ae2[j];
            c2 += b2[j] * Wl[j];
        }
        g_ce[0] = c0; g_ce[1] = c1; g_ce[2] = c2;
    }
    if (t >= 32 && t < 32 + HH) {
        int k = t - 32;
        float cs = 0.f, cd = 0.f, cp = 0.f;
        const float* wr = W2 + k * HH;
        for (int j = 0; j < HH; j++) {
            float w = wr[j];
            cs = fmaf(w, as2[j], cs);
            cd = fmaf(w, ad2[j], cd);
            cp = fmaf(w, Wl[j],  cp);
        }
        g_cs[k] = cs; g_cd[k] = cd; g_cp[k] = cp;
    }
}

// zero g_out (full rows, 8 float4 each) and layer-2 accumulators
__global__ void k_zero() {
    int i = blockIdx.x * blockDim.x + threadIdx.x;
    if (i < NN * (OS / 4))
        reinterpret_cast<float4*>(g_out)[i] = make_float4(0.f, 0.f, 0.f, 0.f);
    if (i < NN) g_acc2[i] = make_float2(0.f, 0.f);
}

// layer-1 edge pass in EMB-SPACE (rank-16 collapse), 4 lanes/edge:
//   ex = exp(lrelu(HS[cat_s] + HD[cat_d] + ea*ce0))
//   out[d,0:16] += ex * emb[cat_s,:]   ;  out[d,16:20] += (ex, ea, 1, 0)
// All 5 red.v4 per edge land in ONE 128B line.
__global__ void k_edge1(const int* __restrict__ src, const int* __restrict__ dst,
                        const float* __restrict__ ea, const int* __restrict__ x_idx,
                        const float* __restrict__ emb) {
    int t = threadIdx.x;
    int idx = blockIdx.x * blockDim.x + t;   // < NE*4 = 12.8M, fits int
    int e = idx >> 2;
    int lane = t & 31;
    int r = lane & 3;
    int cs = 0, d = 0;
    float ex = 0.f;
    if (r == 0) {
        int s = src[e];
        d = dst[e];
        cs = x_idx[s];                        // 4B random gather
        int cd = x_idx[d];                    // 4B random gather
        float a = ea[e];
        float al = __ldg(&g_HS[cs]) + __ldg(&g_HD[cd]) + a * g_ce[0];
        al = (al > 0.f) ? al : 0.2f * al;
        ex = __expf(al);
        red_add_v4(g_out + d * OS + 16, make_float4(ex, a, 1.f, 0.f));
    }
    int ld = lane & ~3;                       // grid exact multiple: all lanes alive
    cs = __shfl_sync(0xffffffffu, cs, ld);
    d  = __shfl_sync(0xffffffffu, d,  ld);
    ex = __shfl_sync(0xffffffffu, ex, ld);
    float4 ev = *reinterpret_cast<const float4*>(emb + cs * EMBD + r * 4);  // L1-hot 9KB
    ev.x *= ex; ev.y *= ex; ev.z *= ex; ev.w *= ex;
    red_add_v4(g_out + d * OS + r * 4, ev);
}

// normalize layer 1 in emb-space, @W1, (+ self-loop), relu(.+b1); layer-2 projections
__global__ void k_mid(const float* __restrict__ b1, const int* __restrict__ x_idx,
                      const float* __restrict__ emb, const float* __restrict__ W1) {
    __shared__ float sW[EMBD * HH];
    int t = threadIdx.x;
    for (int i = t; i < EMBD * HH; i += blockDim.x) sW[i] = W1[i];
    __syncthreads();
    int n = (blockIdx.x * blockDim.x + t) >> 5;
    int lane = t & 31;
    if (n >= NN) return;
    int c = x_idx[n];                          // uniform across warp
    float rowv = g_out[n * OS + lane];         // one 128B line, coalesced
    float embv = (lane < EMBD) ? emb[c * EMBD + lane] : 0.f;
    float den = __shfl_sync(0xffffffffu, rowv, 16);
    float scx = __shfl_sync(0xffffffffu, rowv, 17);
    float scc = __shfl_sync(0xffffffffu, rowv, 18);
    float loop = scx / fmaxf(scc, 1.f);
    float al = __ldg(&g_HS[c]) + __ldg(&g_HD[c]) + loop * g_ce[0];
    al = (al > 0.f) ? al : 0.2f * al;
    float exs = __expf(al);
    // v[lane] = ((E + exs*emb[c]) @ W1)[lane] / (den+exs)
    float acc = 0.f;
#pragma unroll
    for (int j = 0; j < EMBD; j++) {
        float Ej = __shfl_sync(0xffffffffu, rowv, j)
                 + exs * __shfl_sync(0xffffffffu, embv, j);
        acc = fmaf(Ej, sW[j * HH + lane], acc);
    }
    float v = acc / (den + exs + 1e-16f);
    v = fmaxf(v + b1[lane], 0.f);
    float s2 = v * g_cs[lane];
    float d2 = v * g_cd[lane];
    float p  = v * g_cp[lane];
    for (int o = 16; o; o >>= 1) {
        s2 += __shfl_xor_sync(0xffffffffu, s2, o);
        d2 += __shfl_xor_sync(0xffffffffu, d2, o);
        p  += __shfl_xor_sync(0xffffffffu, p,  o);
    }
    if (lane == 0) {
        g_sp[n] = make_float2(s2, p);
        g_hd[n] = d2;
        g_loop[n] = loop;
    }
}

// layer-2 edge pass, 1 thread/edge (scalar projection)
__global__ void k_edge2(const int* __restrict__ src, const int* __restrict__ dst,
                        const float* __restrict__ ea) {
    int e = blockIdx.x * blockDim.x + threadIdx.x;
    if (e >= NE) return;
    int s = src[e], d = dst[e];
    float2 sp = g_sp[s];
    float al = sp.x + g_hd[d] + ea[e] * g_ce[1];
    al = (al > 0.f) ? al : 0.2f * al;
    float ex = __expf(al);
    red_add_v2(&g_acc2[d].x, make_float2(ex * sp.y, ex));
}

// final: add self-loop, normalize, add (b2·Wl + bl)
__global__ void k_final(float* __restrict__ out) {
    int n = blockIdx.x * blockDim.x + threadIdx.x;
    if (n >= NN) return;
    float2 sp = g_sp[n];
    float al = sp.x + g_hd[n] + g_loop[n] * g_ce[1];
    al = (al > 0.f) ? al : 0.2f * al;
    float exs = __expf(al);
    float2 acc = g_acc2[n];
    out[n] = (acc.x + exs * sp.y) / (acc.y + exs + 1e-16f) + g_ce[2];
}

// ---------------- launch ----------------
extern "C" void kernel_launch(void* const* d_in, const int* in_sizes, int n_in,
                              void* d_out, int out_size) {
    const int*   x_idx = (const int*)  d_in[0];
    const int*   ei    = (const int*)  d_in[1];
    const float* ea    = (const float*)d_in[2];
    const float* emb   = (const float*)d_in[3];
    const float* W1    = (const float*)d_in[4];
    const float* as1   = (const float*)d_in[5];
    const float* ad1   = (const float*)d_in[6];
    const float* We1   = (const float*)d_in[7];
    const float* ae1   = (const float*)d_in[8];
    const float* b1    = (const float*)d_in[9];
    const float* W2    = (const float*)d_in[10];
    const float* as2   = (const float*)d_in[11];
    const float* ad2   = (const float*)d_in[12];
    const float* We2   = (const float*)d_in[13];
    const float* ae2   = (const float*)d_in[14];
    const float* b2    = (const float*)d_in[15];
    const float* Wl    = (const float*)d_in[16];
    const float* bl    = (const float*)d_in[17];
    float* out = (float*)d_out;

    const int* src = ei;
    const int* dst = ei + NE;

    const int TB = 256;
    const int gN   = (NN + TB - 1) / TB;
    const int gE   = (NE + TB - 1) / TB;
    const int gNW  = (NN * 32 + TB - 1) / TB;          // warp per node
    const int gED1 = NE * 4 / TB;                      // 4 lanes per edge, exact
    const int gZ   = (NN * (OS / 4) + TB - 1) / TB;

    k_init<<<1, 256>>>(emb, W1, as1, ad1, We1, ae1, We2, ae2, b2, Wl, bl, W2, as2, ad2);
    k_zero<<<gZ, TB>>>();

    // layer 1 (3rd launch -> profiled)
    k_edge1<<<gED1, TB>>>(src, dst, ea, x_idx, emb);
    k_mid<<<gNW, TB>>>(b1, x_idx, emb, W1);

    // layer 2
    k_edge2<<<gE, TB>>>(src, dst, ea);
    k_final<<<gN, TB>>>(out);
}

// round 16
// speedup vs baseline: 2.0872x; 1.1595x over previous
#include <cuda_runtime.h>

#define NN 100000
#define NE 3200000
#define HH 32
#define EMBD 16
#define NCAT 141
#define OS 32   // g_out row stride (floats) = 128B line: [0..15] emb-acc | [16..19] aux | pad

// ---------------- device scratch (static, no allocation) ----------------
__device__ float    g_H[NCAT * HH];             // emb @ W1 (init-time only)
__device__ float    g_HS[NCAT];                 // H · as1 per category (L1-resident)
__device__ float    g_HD[NCAT];                 // H · ad1 per category (L1-resident)
__device__ float    g_hd[NN];                   // layer-2 h2·ad2
__device__ float    g_loop[NN];                 // self-loop attr
__device__ __align__(128) float g_out[NN * OS]; // one 128B line per dst
__device__ float2   g_sp[NN];                   // layer-2 (h2·as2, h2·Wl)
__device__ float2   g_acc2[NN];                 // layer-2 (num, den)
__device__ float    g_ce[3];                    // ce1, ce2, b2·Wl + bl
__device__ float    g_cs[HH];                   // W2 · as2
__device__ float    g_cd[HH];                   // W2 · ad2
__device__ float    g_cp[HH];                   // W2 · Wl

// ---------------- vector reduction helpers (sm_90+) ----------------
__device__ __forceinline__ void red_add_v4(float* p, float4 v) {
    asm volatile("red.global.add.v4.f32 [%0], {%1,%2,%3,%4};"
                 :: "l"(p), "f"(v.x), "f"(v.y), "f"(v.z), "f"(v.w) : "memory");
}
__device__ __forceinline__ void red_add_v2(float* p, float2 v) {
    asm volatile("red.global.add.v2.f32 [%0], {%1,%2};"
                 :: "l"(p), "f"(v.x), "f"(v.y) : "memory");
}

// ---------------- kernels ----------------

// one block: category tables + collapsed constants
__global__ void k_init(const float* emb, const float* W1,
                       const float* as1, const float* ad1,
                       const float* We1, const float* ae1,
                       const float* We2, const float* ae2,
                       const float* b2,  const float* Wl, const float* bl,
                       const float* W2,  const float* as2, const float* ad2) {
    int t = threadIdx.x;
    for (int i = t; i < NCAT * HH; i += blockDim.x) {
        int c = i >> 5, k = i & 31;
        float acc = 0.f;
        const float* er = emb + c * EMBD;
#pragma unroll
        for (int j = 0; j < EMBD; j++) acc = fmaf(er[j], W1[j * HH + k], acc);
        g_H[i] = acc;
    }
    __syncthreads();
    for (int c = t; c < NCAT; c += blockDim.x) {
        float hs = 0.f, hd = 0.f;
        const float* hr = g_H + c * HH;
        for (int j = 0; j < HH; j++) {
            hs = fmaf(hr[j], as1[j], hs);
            hd = fmaf(hr[j], ad1[j], hd);
        }
        g_HS[c] = hs; g_HD[c] = hd;
    }
    if (t == 0) {
        float c0 = 0.f, c1 = 0.f, c2 = bl[0];
        for (int j = 0; j < HH; j++) {
            c0 += We1[j] * ae1[j];
            c1 += We2[j] * ae2[j];
            c2 += b2[j] * Wl[j];
        }
        g_ce[0] = c0; g_ce[1] = c1; g_ce[2] = c2;
    }
    if (t >= 32 && t < 32 + HH) {
        int k = t - 32;
        float cs = 0.f, cd = 0.f, cp = 0.f;
        const float* wr = W2 + k * HH;
        for (int j = 0; j < HH; j++) {
            float w = wr[j];
            cs = fmaf(w, as2[j], cs);
            cd = fmaf(w, ad2[j], cd);
            cp = fmaf(w, Wl[j],  cp);
        }
        g_cs[k] = cs; g_cd[k] = cd; g_cp[k] = cp;
    }
}

// zero g_out rows and layer-2 accumulators
__global__ void k_zero() {
    int i = blockIdx.x * blockDim.x + threadIdx.x;
    if (i < NN * (OS / 4))
        reinterpret_cast<float4*>(g_out)[i] = make_float4(0.f, 0.f, 0.f, 0.f);
    if (i < NN) g_acc2[i] = make_float2(0.f, 0.f);
}

// layer-1 edge pass in EMB-SPACE (rank-16 collapse), 4 lanes/edge:
//   ex = exp(lrelu(HS[cat_s] + HD[cat_d] + ea*ce0))
//   out[d,0:16] += ex * emb[cat_s,:]   ;  out[d,16:20] += (ex, ea, 1, 0)
__global__ void k_edge1(const int* __restrict__ src, const int* __restrict__ dst,
                        const float* __restrict__ ea, const int* __restrict__ x_idx,
                        const float* __restrict__ emb) {
    int t = threadIdx.x;
    int idx = blockIdx.x * blockDim.x + t;   // < NE*4 = 12.8M, fits int
    int e = idx >> 2;
    int lane = t & 31;
    int r = lane & 3;
    int cs = 0, d = 0;
    float ex = 0.f;
    if (r == 0) {
        int s = src[e];
        d = dst[e];
        cs = x_idx[s];
        int cd = x_idx[d];
        float a = ea[e];
        float al = __ldg(&g_HS[cs]) + __ldg(&g_HD[cd]) + a * g_ce[0];
        al = (al > 0.f) ? al : 0.2f * al;
        ex = __expf(al);
        red_add_v4(g_out + d * OS + 16, make_float4(ex, a, 1.f, 0.f));
    }
    int ld = lane & ~3;
    cs = __shfl_sync(0xffffffffu, cs, ld);
    d  = __shfl_sync(0xffffffffu, d,  ld);
    ex = __shfl_sync(0xffffffffu, ex, ld);
    float4 ev = *reinterpret_cast<const float4*>(emb + cs * EMBD + r * 4);
    ev.x *= ex; ev.y *= ex; ev.z *= ex; ev.w *= ex;
    red_add_v4(g_out + d * OS + r * 4, ev);
}

// THREAD-PER-NODE normalize + @W1 + self-loop + relu(.+b1) + layer-2 projections.
// Zero shuffles; all small tables in smem with uniform broadcast access.
__global__ void k_mid(const float* __restrict__ b1, const int* __restrict__ x_idx,
                      const float* __restrict__ emb, const float* __restrict__ W1) {
    __shared__ float sW[EMBD * HH];
    __shared__ float sb[HH], scs[HH], scd[HH], scp[HH];
    int t = threadIdx.x;
    for (int i = t; i < EMBD * HH; i += blockDim.x) sW[i] = W1[i];
    if (t < HH) { sb[t] = b1[t]; scs[t] = g_cs[t]; scd[t] = g_cd[t]; scp[t] = g_cp[t]; }
    __syncthreads();
    int n = blockIdx.x * blockDim.x + t;
    if (n >= NN) return;
    // load this node's 128B row: 4 float4 of emb-acc + 1 float4 aux
    const float4* row = reinterpret_cast<const float4*>(g_out + n * OS);
    float4 e0 = row[0], e1 = row[1], e2 = row[2], e3 = row[3];
    float4 aux = row[4];
    float den = aux.x;
    float loop = aux.y / fmaxf(aux.z, 1.f);
    int c = x_idx[n];
    float al = __ldg(&g_HS[c]) + __ldg(&g_HD[c]) + loop * g_ce[0];
    al = (al > 0.f) ? al : 0.2f * al;
    float exs = __expf(al);
    // E = acc + exs * emb[c]
    const float4* ec = reinterpret_cast<const float4*>(emb + c * EMBD);
    float4 m0 = ec[0], m1 = ec[1], m2 = ec[2], m3 = ec[3];
    float E[EMBD];
    E[0]=fmaf(exs,m0.x,e0.x); E[1]=fmaf(exs,m0.y,e0.y); E[2]=fmaf(exs,m0.z,e0.z); E[3]=fmaf(exs,m0.w,e0.w);
    E[4]=fmaf(exs,m1.x,e1.x); E[5]=fmaf(exs,m1.y,e1.y); E[6]=fmaf(exs,m1.z,e1.z); E[7]=fmaf(exs,m1.w,e1.w);
    E[8]=fmaf(exs,m2.x,e2.x); E[9]=fmaf(exs,m2.y,e2.y); E[10]=fmaf(exs,m2.z,e2.z); E[11]=fmaf(exs,m2.w,e2.w);
    E[12]=fmaf(exs,m3.x,e3.x); E[13]=fmaf(exs,m3.y,e3.y); E[14]=fmaf(exs,m3.z,e3.z); E[15]=fmaf(exs,m3.w,e3.w);
    float inv = 1.f / (den + exs + 1e-16f);
    float s2 = 0.f, d2 = 0.f, p = 0.f;
#pragma unroll 4
    for (int j = 0; j < HH; j++) {
        float acc = 0.f;
#pragma unroll
        for (int k = 0; k < EMBD; k++) acc = fmaf(E[k], sW[k * HH + j], acc);
        float v = fmaxf(acc * inv + sb[j], 0.f);
        s2 = fmaf(v, scs[j], s2);
        d2 = fmaf(v, scd[j], d2);
        p  = fmaf(v, scp[j], p);
    }
    g_sp[n] = make_float2(s2, p);
    g_hd[n] = d2;
    g_loop[n] = loop;
}

// layer-2 edge pass, 1 thread/edge (scalar projection)
__global__ void k_edge2(const int* __restrict__ src, const int* __restrict__ dst,
                        const float* __restrict__ ea) {
    int e = blockIdx.x * blockDim.x + threadIdx.x;
    if (e >= NE) return;
    int s = src[e], d = dst[e];
    float2 sp = g_sp[s];
    float al = sp.x + g_hd[d] + ea[e] * g_ce[1];
    al = (al > 0.f) ? al : 0.2f * al;
    float ex = __expf(al);
    red_add_v2(&g_acc2[d].x, make_float2(ex * sp.y, ex));
}

// final: add self-loop, normalize, add (b2·Wl + bl)
__global__ void k_final(float* __restrict__ out) {
    int n = blockIdx.x * blockDim.x + threadIdx.x;
    if (n >= NN) return;
    float2 sp = g_sp[n];
    float al = sp.x + g_hd[n] + g_loop[n] * g_ce[1];
    al = (al > 0.f) ? al : 0.2f * al;
    float exs = __expf(al);
    float2 acc = g_acc2[n];
    out[n] = (acc.x + exs * sp.y) / (acc.y + exs + 1e-16f) + g_ce[2];
}

// ---------------- launch ----------------
extern "C" void kernel_launch(void* const* d_in, const int* in_sizes, int n_in,
                              void* d_out, int out_size) {
    const int*   x_idx = (const int*)  d_in[0];
    const int*   ei    = (const int*)  d_in[1];
    const float* ea    = (const float*)d_in[2];
    const float* emb   = (const float*)d_in[3];
    const float* W1    = (const float*)d_in[4];
    const float* as1   = (const float*)d_in[5];
    const float* ad1   = (const float*)d_in[6];
    const float* We1   = (const float*)d_in[7];
    const float* ae1   = (const float*)d_in[8];
    const float* b1    = (const float*)d_in[9];
    const float* W2    = (const float*)d_in[10];
    const float* as2   = (const float*)d_in[11];
    const float* ad2   = (const float*)d_in[12];
    const float* We2   = (const float*)d_in[13];
    const float* ae2   = (const float*)d_in[14];
    const float* b2    = (const float*)d_in[15];
    const float* Wl    = (const float*)d_in[16];
    const float* bl    = (const float*)d_in[17];
    float* out = (float*)d_out;

    const int* src = ei;
    const int* dst = ei + NE;

    const int TB = 256;
    const int gN   = (NN + TB - 1) / TB;
    const int gE   = (NE + TB - 1) / TB;
    const int gED1 = NE * 4 / TB;                      // 4 lanes per edge, exact
    const int gZ   = (NN * (OS / 4) + TB - 1) / TB;

    k_init<<<1, 256>>>(emb, W1, as1, ad1, We1, ae1, We2, ae2, b2, Wl, bl, W2, as2, ad2);
    k_zero<<<gZ, TB>>>();

    // layer 1 (3rd launch -> profiled)
    k_edge1<<<gED1, TB>>>(src, dst, ea, x_idx, emb);
    k_mid<<<gN, TB>>>(b1, x_idx, emb, W1);

    // layer 2
    k_edge2<<<gE, TB>>>(src, dst, ea);
    k_final<<<gN, TB>>>(out);
}